// round 4
// baseline (speedup 1.0000x reference)
#include <cuda_runtime.h>
#include <cstring>

typedef unsigned long long ull;

#define NGOAL 16384
#define NOBS  65536
#define NTASK 8192
#define NE1   1048576
#define NE2   1048576
#define NB    256
#define FDIM  128
#define SDIM  64
#define CAP1  64
#define CAP2  256

// ---------------- scratch (device globals; no allocation allowed) ----------------
__device__ __align__(16) float g_goalT[NGOAL * SDIM];
__device__ __align__(16) float g_acc1[(size_t)NOBS * SDIM];
__device__ __align__(16) float g_x1[(size_t)NOBS * SDIM];
__device__ __align__(16) float g_acc2[NTASK * SDIM];
__device__ float g_x2[NTASK];
__device__ int g_deg1[NOBS];
__device__ int g_deg2[NTASK];
__device__ __align__(16) int g_slot1[(size_t)NOBS * CAP1];
__device__ __align__(16) int g_slot2[(size_t)NTASK * CAP2];
__device__ __align__(16) float2 g_W1d[FDIM * SDIM];   // (w,w) duplicated pairs
__device__ __align__(16) float2 g_W2d[SDIM * SDIM];

#define FFMA2(d, a, b) \
    asm("fma.rn.f32x2 %0, %1, %2, %0;" : "+l"(d) : "l"(a), "l"(b))

// ================= weight pair-duplication (once per launch) =================
__global__ void dup_weights(const float* __restrict__ W1, const float* __restrict__ W2) {
    int i = blockIdx.x * blockDim.x + threadIdx.x;
    if (i < FDIM * SDIM) { float w = W1[i]; g_W1d[i] = make_float2(w, w); }
    if (i < SDIM * SDIM) { float w = W2[i]; g_W2d[i] = make_float2(w, w); }
}

// ================= GEMM: Y[M,64] = f(X[M,K]) @ W[K,64] (+b), packed f32x2 =================
// Block: 128 rows x 64 cols, 256 threads. tm=lane(0..31) -> M-pairs 2tm,2tm+1 (rows 4tm..4tm+3).
// tn=warp(0..7) -> cols 8tn..8tn+7. Per k: 1 LDS.128 (A, all lanes distinct) +
// 4 uniform LDG.128 (W-dup, coalesced broadcast, L1-hot) + 16 FFMA2.
// A double-buffered in smem via register staging (one sync per chunk).
template <int K, bool RELU_IN, bool RELU_OUT, bool BIAS>
__global__ void __launch_bounds__(256) gemm_f2(const float* __restrict__ X,
                                               const float2* __restrict__ Wd,
                                               const float* __restrict__ b,
                                               float* __restrict__ Y) {
    __shared__ float Af[2][32 * 132];   // [buf][k*132 + m], 33.8 KB

    const int tid = threadIdx.x;
    const int tm = tid & 31;
    const int tn = tid >> 5;
    const int m0 = blockIdx.x * 128;
    const int f4 = tid & 7;        // staging: k-subgroup
    const int mrow = tid >> 3;     // staging: row 0..31 (+32*it)

    ull acc[2][8];
#pragma unroll
    for (int c = 0; c < 8; c++) {
        float bv = BIAS ? b[8 * tn + c] : 0.0f;
        float2 bb = make_float2(bv, bv);
        ull bu; memcpy(&bu, &bb, 8);
        acc[0][c] = bu; acc[1][c] = bu;
    }

    const int NC = K / 32;
    float4 st[4];

    // ---- stage chunk 0 ----
#pragma unroll
    for (int it = 0; it < 4; it++)
        st[it] = *(const float4*)(X + (size_t)(m0 + mrow + 32 * it) * K + 4 * f4);
#pragma unroll
    for (int it = 0; it < 4; it++) {
        float4 v = st[it];
        if (RELU_IN) {
            v.x = fmaxf(v.x, 0.0f); v.y = fmaxf(v.y, 0.0f);
            v.z = fmaxf(v.z, 0.0f); v.w = fmaxf(v.w, 0.0f);
        }
        int m = mrow + 32 * it;
        Af[0][(4 * f4 + 0) * 132 + m] = v.x;
        Af[0][(4 * f4 + 1) * 132 + m] = v.y;
        Af[0][(4 * f4 + 2) * 132 + m] = v.z;
        Af[0][(4 * f4 + 3) * 132 + m] = v.w;
    }
    __syncthreads();

    for (int c = 0; c < NC; c++) {
        // prefetch next chunk into registers (latency overlaps compute)
        if (c + 1 < NC) {
#pragma unroll
            for (int it = 0; it < 4; it++)
                st[it] = *(const float4*)(X + (size_t)(m0 + mrow + 32 * it) * K +
                                          32 * (c + 1) + 4 * f4);
        }
        const float* A = Af[c & 1];
        const float2* Wk = Wd + (size_t)(32 * c) * 64;
#pragma unroll 4
        for (int k = 0; k < 32; k++) {
            ulonglong2 a = *(const ulonglong2*)(A + k * 132 + 4 * tm);
            const ulonglong2* wp = (const ulonglong2*)(Wk + k * 64 + 8 * tn);
            ulonglong2 w0 = __ldg(wp);
            ulonglong2 w1 = __ldg(wp + 1);
            ulonglong2 w2 = __ldg(wp + 2);
            ulonglong2 w3 = __ldg(wp + 3);
            FFMA2(acc[0][0], a.x, w0.x); FFMA2(acc[0][1], a.x, w0.y);
            FFMA2(acc[0][2], a.x, w1.x); FFMA2(acc[0][3], a.x, w1.y);
            FFMA2(acc[0][4], a.x, w2.x); FFMA2(acc[0][5], a.x, w2.y);
            FFMA2(acc[0][6], a.x, w3.x); FFMA2(acc[0][7], a.x, w3.y);
            FFMA2(acc[1][0], a.y, w0.x); FFMA2(acc[1][1], a.y, w0.y);
            FFMA2(acc[1][2], a.y, w1.x); FFMA2(acc[1][3], a.y, w1.y);
            FFMA2(acc[1][4], a.y, w2.x); FFMA2(acc[1][5], a.y, w2.y);
            FFMA2(acc[1][6], a.y, w3.x); FFMA2(acc[1][7], a.y, w3.y);
        }
        if (c + 1 < NC) {
#pragma unroll
            for (int it = 0; it < 4; it++) {
                float4 v = st[it];
                if (RELU_IN) {
                    v.x = fmaxf(v.x, 0.0f); v.y = fmaxf(v.y, 0.0f);
                    v.z = fmaxf(v.z, 0.0f); v.w = fmaxf(v.w, 0.0f);
                }
                int m = mrow + 32 * it;
                float* B = Af[(c + 1) & 1];
                B[(4 * f4 + 0) * 132 + m] = v.x;
                B[(4 * f4 + 1) * 132 + m] = v.y;
                B[(4 * f4 + 2) * 132 + m] = v.z;
                B[(4 * f4 + 3) * 132 + m] = v.w;
            }
            __syncthreads();
        }
    }

    // ---- epilogue: pairs 2tm+p -> rows 4tm+2p, 4tm+2p+1; cols 8tn..8tn+7 ----
#pragma unroll
    for (int p = 0; p < 2; p++) {
        int r = m0 + 4 * tm + 2 * p;
        float2 v[8];
#pragma unroll
        for (int c = 0; c < 8; c++) memcpy(&v[c], &acc[p][c], 8);
        float4 lo0 = make_float4(v[0].x, v[1].x, v[2].x, v[3].x);
        float4 lo1 = make_float4(v[4].x, v[5].x, v[6].x, v[7].x);
        float4 hi0 = make_float4(v[0].y, v[1].y, v[2].y, v[3].y);
        float4 hi1 = make_float4(v[4].y, v[5].y, v[6].y, v[7].y);
        if (RELU_OUT) {
            lo0.x = fmaxf(lo0.x, 0.0f); lo0.y = fmaxf(lo0.y, 0.0f);
            lo0.z = fmaxf(lo0.z, 0.0f); lo0.w = fmaxf(lo0.w, 0.0f);
            lo1.x = fmaxf(lo1.x, 0.0f); lo1.y = fmaxf(lo1.y, 0.0f);
            lo1.z = fmaxf(lo1.z, 0.0f); lo1.w = fmaxf(lo1.w, 0.0f);
            hi0.x = fmaxf(hi0.x, 0.0f); hi0.y = fmaxf(hi0.y, 0.0f);
            hi0.z = fmaxf(hi0.z, 0.0f); hi0.w = fmaxf(hi0.w, 0.0f);
            hi1.x = fmaxf(hi1.x, 0.0f); hi1.y = fmaxf(hi1.y, 0.0f);
            hi1.z = fmaxf(hi1.z, 0.0f); hi1.w = fmaxf(hi1.w, 0.0f);
        }
        *(float4*)(Y + (size_t)r * 64 + 8 * tn) = lo0;
        *(float4*)(Y + (size_t)r * 64 + 8 * tn + 4) = lo1;
        *(float4*)(Y + (size_t)(r + 1) * 64 + 8 * tn) = hi0;
        *(float4*)(Y + (size_t)(r + 1) * 64 + 8 * tn + 4) = hi1;
    }
}

// ================= CSR-bucket build =================
__global__ void zero_deg() {
    int i = blockIdx.x * blockDim.x + threadIdx.x;
    if (i < NOBS) g_deg1[i] = 0;
    else if (i < NOBS + NTASK) g_deg2[i - NOBS] = 0;
}

__global__ void fill_csr(const int* __restrict__ s1, const int* __restrict__ d1,
                         const int* __restrict__ s2, const int* __restrict__ d2) {
    int i = blockIdx.x * blockDim.x + threadIdx.x;
    if (i < NE1) {
        int d = d1[i];
        int p = atomicAdd(&g_deg1[d], 1);
        if (p < CAP1) g_slot1[(size_t)d * CAP1 + p] = s1[i];
    } else {
        int e = i - NE1;
        int d = d2[e];
        int p = atomicAdd(&g_deg2[d], 1);
        if (p < CAP2) g_slot2[(size_t)d * CAP2 + p] = s2[e];
    }
}

// ================= gather: out[d] = base[d] + sum_i table[slot[d][i]] =================
// Half-warp per destination; 4-way ILP on the L2-latency chain, int4 slot loads.
template <int CAP>
__global__ void __launch_bounds__(256) gather(const int* __restrict__ deg,
                                              const int* __restrict__ slot,
                                              const float4* __restrict__ table,
                                              const float4* __restrict__ base,
                                              float4* __restrict__ out) {
    const int hw = (blockIdx.x * blockDim.x + threadIdx.x) >> 4;
    const int q = threadIdx.x & 15;
    int dg = deg[hw];
    if (dg > CAP) dg = CAP;
    const int* sl = slot + (size_t)hw * CAP;
    float4 v = base[hw * 16 + q];
    float4 u1 = make_float4(0.f, 0.f, 0.f, 0.f);
    float4 u2 = make_float4(0.f, 0.f, 0.f, 0.f);
    float4 u3 = make_float4(0.f, 0.f, 0.f, 0.f);
    int i = 0;
    for (; i + 4 <= dg; i += 4) {
        int4 s = *(const int4*)(sl + i);
        float4 t0 = table[(size_t)s.x * 16 + q];
        float4 t1 = table[(size_t)s.y * 16 + q];
        float4 t2 = table[(size_t)s.z * 16 + q];
        float4 t3 = table[(size_t)s.w * 16 + q];
        v.x += t0.x;  v.y += t0.y;  v.z += t0.z;  v.w += t0.w;
        u1.x += t1.x; u1.y += t1.y; u1.z += t1.z; u1.w += t1.w;
        u2.x += t2.x; u2.y += t2.y; u2.z += t2.z; u2.w += t2.w;
        u3.x += t3.x; u3.y += t3.y; u3.z += t3.z; u3.w += t3.w;
    }
    for (; i < dg; i++) {
        float4 t = table[(size_t)__ldg(sl + i) * 16 + q];
        v.x += t.x; v.y += t.y; v.z += t.z; v.w += t.w;
    }
    v.x += u1.x + u2.x + u3.x;
    v.y += u1.y + u2.y + u3.y;
    v.z += u1.z + u2.z + u3.z;
    v.w += u1.w + u2.w + u3.w;
    out[hw * 16 + q] = v;
}

// ================= task head: x2[t] = relu(acc2[t]@W3+b3) @ W4 + b4 =================
__global__ void __launch_bounds__(256) task_head(const float* __restrict__ acc2,
                                                 const float* __restrict__ W3,
                                                 const float* __restrict__ b3,
                                                 const float* __restrict__ W4,
                                                 const float* __restrict__ b4,
                                                 float* __restrict__ x2) {
    __shared__ float W3sh[SDIM * SDIM];
    __shared__ float b3sh[SDIM];
    __shared__ float W4sh[SDIM];
    for (int i = threadIdx.x; i < SDIM * SDIM; i += blockDim.x) W3sh[i] = W3[i];
    if (threadIdx.x < SDIM) { b3sh[threadIdx.x] = b3[threadIdx.x]; W4sh[threadIdx.x] = W4[threadIdx.x]; }
    __syncthreads();

    const int warp = threadIdx.x >> 5;
    const int lane = threadIdx.x & 31;
    const int t = blockIdx.x * (blockDim.x >> 5) + warp;

    const float* row = acc2 + (size_t)t * SDIM;
    float s0 = b3sh[lane];
    float s1 = b3sh[lane + 32];
#pragma unroll 4
    for (int k = 0; k < SDIM; k++) {
        float a = __ldg(row + k);
        s0 = fmaf(a, W3sh[k * SDIM + lane], s0);
        s1 = fmaf(a, W3sh[k * SDIM + lane + 32], s1);
    }
    float p = fmaxf(s0, 0.0f) * W4sh[lane] + fmaxf(s1, 0.0f) * W4sh[lane + 32];
#pragma unroll
    for (int o = 16; o; o >>= 1) p += __shfl_xor_sync(0xffffffffu, p, o);
    if (lane == 0) x2[t] = p + b4[0];
}

// ================= pooling + critic: one warp per graph =================
__global__ void __launch_bounds__(256) pool_critic(const float* __restrict__ x2,
                                                   const float* __restrict__ Wc1,
                                                   const float* __restrict__ bc1,
                                                   const float* __restrict__ Wc2,
                                                   const float* __restrict__ bc2,
                                                   float* __restrict__ out) {
    const int warp = (blockIdx.x * blockDim.x + threadIdx.x) >> 5;
    const int lane = threadIdx.x & 31;
    if (warp >= NB) return;
    float v = x2[warp * 32 + lane];
    float mx = v, sm = v;
#pragma unroll
    for (int o = 16; o; o >>= 1) {
        mx = fmaxf(mx, __shfl_xor_sync(0xffffffffu, mx, o));
        sm += __shfl_xor_sync(0xffffffffu, sm, o);
    }
    if (lane == 0) {
        float mean = sm * (1.0f / 32.0f);
        float r = bc2[0];
#pragma unroll
        for (int i = 0; i < 8; i++) {
            float h = fmaxf(fmaf(mx, Wc1[i], fmaf(mean, Wc1[8 + i], bc1[i])), 0.0f);
            r = fmaf(h, Wc2[i], r);
        }
        out[warp] = r;
    }
}

extern "C" void kernel_launch(void* const* d_in, const int* in_sizes, int n_in,
                              void* d_out, int out_size) {
    const float* x_goal = (const float*)d_in[0];
    const float* x_obs  = (const float*)d_in[1];
    const float* x_task = (const float*)d_in[2];
    const int* ei_go_src = (const int*)d_in[3];
    const int* ei_go_dst = (const int*)d_in[4];
    const int* ei_ot_src = (const int*)d_in[5];
    const int* ei_ot_dst = (const int*)d_in[6];
    // d_in[7] = task_batch (contiguous 32/graph; unused)
    const float* W1  = (const float*)d_in[8];
    const float* b1  = (const float*)d_in[9];
    const float* W2  = (const float*)d_in[10];
    const float* b2  = (const float*)d_in[11];
    const float* W3  = (const float*)d_in[12];
    const float* b3  = (const float*)d_in[13];
    const float* W4  = (const float*)d_in[14];
    const float* b4  = (const float*)d_in[15];
    const float* Wc1 = (const float*)d_in[16];
    const float* bc1 = (const float*)d_in[17];
    const float* Wc2 = (const float*)d_in[18];
    const float* bc2 = (const float*)d_in[19];
    float* out = (float*)d_out;

    float *goalT, *acc1, *x1, *acc2, *x2;
    int *deg1, *deg2, *slot1, *slot2;
    float2 *W1d, *W2d;
    cudaGetSymbolAddress((void**)&goalT, g_goalT);
    cudaGetSymbolAddress((void**)&acc1, g_acc1);
    cudaGetSymbolAddress((void**)&x1, g_x1);
    cudaGetSymbolAddress((void**)&acc2, g_acc2);
    cudaGetSymbolAddress((void**)&x2, g_x2);
    cudaGetSymbolAddress((void**)&deg1, g_deg1);
    cudaGetSymbolAddress((void**)&deg2, g_deg2);
    cudaGetSymbolAddress((void**)&slot1, g_slot1);
    cudaGetSymbolAddress((void**)&slot2, g_slot2);
    cudaGetSymbolAddress((void**)&W1d, g_W1d);
    cudaGetSymbolAddress((void**)&W2d, g_W2d);

    // --- prep: weight duplication + CSR buckets ---
    dup_weights<<<(FDIM * SDIM + 255) / 256, 256>>>(W1, W2);
    zero_deg<<<(NOBS + NTASK) / 256, 256>>>();
    fill_csr<<<(NE1 + NE2) / 256, 256>>>(ei_go_src, ei_go_dst, ei_ot_src, ei_ot_dst);

    // --- goalT = x_goal @ W1 (W1 pushed through aggregation) ---
    gemm_f2<FDIM, false, false, false><<<NGOAL / 128, 256>>>(x_goal, W1d, b1, goalT);
    // --- acc1 = x_obs @ W1 + b1 ---
    gemm_f2<FDIM, false, false, true><<<NOBS / 128, 256>>>(x_obs, W1d, b1, acc1);
    // --- acc1[d] += sum goalT[src in bucket(d)] ---
    gather<CAP1><<<NOBS * 16 / 256, 256>>>(deg1, slot1, (const float4*)goalT,
                                           (const float4*)acc1, (float4*)acc1);
    // --- x1 = relu(relu(acc1) @ W2 + b2) ---
    gemm_f2<SDIM, true, true, true><<<NOBS / 128, 256>>>(acc1, W2d, b2, x1);
    // --- acc2[d] = x_task[d] + sum x1[src in bucket(d)] ---
    gather<CAP2><<<NTASK * 16 / 256, 256>>>(deg2, slot2, (const float4*)x1,
                                            (const float4*)x_task, (float4*)acc2);
    // --- x2[t] = relu(acc2[t]@W3+b3) @ W4 + b4 ---
    task_head<<<NTASK / 8, 256>>>(acc2, W3, b3, W4, b4, x2);
    // --- per-graph max/mean pool + critic ---
    pool_critic<<<(NB * 32 + 255) / 256, 256>>>(x2, Wc1, bc1, Wc2, bc2, out);
}

// round 5
// speedup vs baseline: 1.4474x; 1.4474x over previous
#include <cuda_runtime.h>
#include <cstring>

typedef unsigned long long ull;

#define NGOAL 16384
#define NOBS  65536
#define NTASK 8192
#define NE1   1048576
#define NE2   1048576
#define NB    256
#define FDIM  128
#define SDIM  64
#define CAP1  64
#define CAP2  256

// ---------------- scratch (device globals; no allocation allowed) ----------------
__device__ __align__(16) float g_goalT[NGOAL * SDIM];
__device__ __align__(16) float g_acc1[(size_t)NOBS * SDIM];
__device__ __align__(16) float g_x1[(size_t)NOBS * SDIM];
__device__ __align__(16) float g_acc2[NTASK * SDIM];
__device__ float g_x2[NTASK];
__device__ int g_deg1[NOBS];
__device__ int g_deg2[NTASK];
__device__ __align__(16) int g_slot1[(size_t)NOBS * CAP1];
__device__ __align__(16) int g_slot2[(size_t)NTASK * CAP2];

#define FFMA2(d, a, b) \
    asm("fma.rn.f32x2 %0, %1, %2, %0;" : "+l"(d) : "l"(a), "l"(b))

// ================= GEMM: Y[M,64] = f(X[M,K]) @ W[K,64] (+b), packed f32x2 =================
// Block: 128 rows x 64 cols, 256 threads, K-chunk 16, A+W double-buffered in smem
// with register prefetch (one __syncthreads per chunk).
// Thread: tm=lane -> M-pairs 2tm,2tm+1 (rows 4tm..4tm+3); tn=warp -> cols 8tn..8tn+7.
// Per k: 1 LDS.128 A (32 lanes distinct, conflict-free) + 4 LDS.128 W (warp-uniform
// broadcast) + 16 FFMA2.
template <int K, bool RELU_IN, bool RELU_OUT, bool BIAS>
__global__ void __launch_bounds__(256, 2) gemm_v5(const float* __restrict__ X,
                                                  const float* __restrict__ W,
                                                  const float* __restrict__ b,
                                                  float* __restrict__ Y) {
    __shared__ float Af[2][16 * 132];     // [buf][k*132 + m]  (2 x 8.45 KB)
    __shared__ float2 Wd[2][16][64];      // duplicated pairs  (2 x 8 KB)

    const int tid = threadIdx.x;
    const int tm = tid & 31;
    const int tn = tid >> 5;
    const int m0 = blockIdx.x * 128;
    // A staging: idx = tid + 256*it -> row m = idx>>2 (0..127), k-quad f4 = idx&3
    const int sf4 = tid & 3;
    const int sm = tid >> 2;
    // W staging: k = tid>>4 (0..15), j4 = tid&15
    const int wk = tid >> 4;
    const int wj4 = tid & 15;

    ull acc[2][8];
#pragma unroll
    for (int c = 0; c < 8; c++) {
        float bv = BIAS ? b[8 * tn + c] : 0.0f;
        float2 bb = make_float2(bv, bv);
        ull bu; memcpy(&bu, &bb, 8);
        acc[0][c] = bu; acc[1][c] = bu;
    }

    const int NC = K / 16;

    // ---- stage chunk 0 ----
    {
#pragma unroll
        for (int it = 0; it < 2; it++) {
            int m = sm + 64 * it;
            float4 v = *(const float4*)(X + (size_t)(m0 + m) * K + 4 * sf4);
            if (RELU_IN) {
                v.x = fmaxf(v.x, 0.0f); v.y = fmaxf(v.y, 0.0f);
                v.z = fmaxf(v.z, 0.0f); v.w = fmaxf(v.w, 0.0f);
            }
            Af[0][(4 * sf4 + 0) * 132 + m] = v.x;
            Af[0][(4 * sf4 + 1) * 132 + m] = v.y;
            Af[0][(4 * sf4 + 2) * 132 + m] = v.z;
            Af[0][(4 * sf4 + 3) * 132 + m] = v.w;
        }
        float4 w = *(const float4*)(W + (size_t)wk * 64 + 4 * wj4);
        Wd[0][wk][4 * wj4 + 0] = make_float2(w.x, w.x);
        Wd[0][wk][4 * wj4 + 1] = make_float2(w.y, w.y);
        Wd[0][wk][4 * wj4 + 2] = make_float2(w.z, w.z);
        Wd[0][wk][4 * wj4 + 3] = make_float2(w.w, w.w);
    }
    __syncthreads();

    for (int c = 0; c < NC; c++) {
        float4 pa0, pa1, pw;
        if (c + 1 < NC) {   // prefetch next chunk into registers
            int kc = 16 * (c + 1);
            pa0 = *(const float4*)(X + (size_t)(m0 + sm) * K + kc + 4 * sf4);
            pa1 = *(const float4*)(X + (size_t)(m0 + sm + 64) * K + kc + 4 * sf4);
            pw  = *(const float4*)(W + (size_t)(kc + wk) * 64 + 4 * wj4);
        }
        const float* A = Af[c & 1];
        const float2(*Wk)[64] = Wd[c & 1];
#pragma unroll
        for (int k = 0; k < 16; k++) {
            ulonglong2 a = *(const ulonglong2*)(A + k * 132 + 4 * tm);
            const ulonglong2* wp = (const ulonglong2*)(&Wk[k][8 * tn]);
            ulonglong2 w0 = wp[0];
            ulonglong2 w1 = wp[1];
            ulonglong2 w2 = wp[2];
            ulonglong2 w3 = wp[3];
            FFMA2(acc[0][0], a.x, w0.x); FFMA2(acc[0][1], a.x, w0.y);
            FFMA2(acc[0][2], a.x, w1.x); FFMA2(acc[0][3], a.x, w1.y);
            FFMA2(acc[0][4], a.x, w2.x); FFMA2(acc[0][5], a.x, w2.y);
            FFMA2(acc[0][6], a.x, w3.x); FFMA2(acc[0][7], a.x, w3.y);
            FFMA2(acc[1][0], a.y, w0.x); FFMA2(acc[1][1], a.y, w0.y);
            FFMA2(acc[1][2], a.y, w1.x); FFMA2(acc[1][3], a.y, w1.y);
            FFMA2(acc[1][4], a.y, w2.x); FFMA2(acc[1][5], a.y, w2.y);
            FFMA2(acc[1][6], a.y, w3.x); FFMA2(acc[1][7], a.y, w3.y);
        }
        if (c + 1 < NC) {
            float* B = Af[(c + 1) & 1];
            float4 v = pa0;
            if (RELU_IN) {
                v.x = fmaxf(v.x, 0.0f); v.y = fmaxf(v.y, 0.0f);
                v.z = fmaxf(v.z, 0.0f); v.w = fmaxf(v.w, 0.0f);
            }
            B[(4 * sf4 + 0) * 132 + sm] = v.x;
            B[(4 * sf4 + 1) * 132 + sm] = v.y;
            B[(4 * sf4 + 2) * 132 + sm] = v.z;
            B[(4 * sf4 + 3) * 132 + sm] = v.w;
            v = pa1;
            if (RELU_IN) {
                v.x = fmaxf(v.x, 0.0f); v.y = fmaxf(v.y, 0.0f);
                v.z = fmaxf(v.z, 0.0f); v.w = fmaxf(v.w, 0.0f);
            }
            B[(4 * sf4 + 0) * 132 + sm + 64] = v.x;
            B[(4 * sf4 + 1) * 132 + sm + 64] = v.y;
            B[(4 * sf4 + 2) * 132 + sm + 64] = v.z;
            B[(4 * sf4 + 3) * 132 + sm + 64] = v.w;
            float2(*WB)[64] = Wd[(c + 1) & 1];
            WB[wk][4 * wj4 + 0] = make_float2(pw.x, pw.x);
            WB[wk][4 * wj4 + 1] = make_float2(pw.y, pw.y);
            WB[wk][4 * wj4 + 2] = make_float2(pw.z, pw.z);
            WB[wk][4 * wj4 + 3] = make_float2(pw.w, pw.w);
            __syncthreads();
        }
    }

    // ---- epilogue: pairs 2tm+p -> rows 4tm+2p, 4tm+2p+1; cols 8tn..8tn+7 ----
#pragma unroll
    for (int p = 0; p < 2; p++) {
        int r = m0 + 4 * tm + 2 * p;
        float2 v[8];
#pragma unroll
        for (int c = 0; c < 8; c++) memcpy(&v[c], &acc[p][c], 8);
        float4 lo0 = make_float4(v[0].x, v[1].x, v[2].x, v[3].x);
        float4 lo1 = make_float4(v[4].x, v[5].x, v[6].x, v[7].x);
        float4 hi0 = make_float4(v[0].y, v[1].y, v[2].y, v[3].y);
        float4 hi1 = make_float4(v[4].y, v[5].y, v[6].y, v[7].y);
        if (RELU_OUT) {
            lo0.x = fmaxf(lo0.x, 0.0f); lo0.y = fmaxf(lo0.y, 0.0f);
            lo0.z = fmaxf(lo0.z, 0.0f); lo0.w = fmaxf(lo0.w, 0.0f);
            lo1.x = fmaxf(lo1.x, 0.0f); lo1.y = fmaxf(lo1.y, 0.0f);
            lo1.z = fmaxf(lo1.z, 0.0f); lo1.w = fmaxf(lo1.w, 0.0f);
            hi0.x = fmaxf(hi0.x, 0.0f); hi0.y = fmaxf(hi0.y, 0.0f);
            hi0.z = fmaxf(hi0.z, 0.0f); hi0.w = fmaxf(hi0.w, 0.0f);
            hi1.x = fmaxf(hi1.x, 0.0f); hi1.y = fmaxf(hi1.y, 0.0f);
            hi1.z = fmaxf(hi1.z, 0.0f); hi1.w = fmaxf(hi1.w, 0.0f);
        }
        *(float4*)(Y + (size_t)r * 64 + 8 * tn) = lo0;
        *(float4*)(Y + (size_t)r * 64 + 8 * tn + 4) = lo1;
        *(float4*)(Y + (size_t)(r + 1) * 64 + 8 * tn) = hi0;
        *(float4*)(Y + (size_t)(r + 1) * 64 + 8 * tn + 4) = hi1;
    }
}

// ================= CSR-bucket build =================
__global__ void zero_deg() {
    int i = blockIdx.x * blockDim.x + threadIdx.x;
    if (i < NOBS) g_deg1[i] = 0;
    else if (i < NOBS + NTASK) g_deg2[i - NOBS] = 0;
}

__global__ void fill_csr(const int* __restrict__ s1, const int* __restrict__ d1,
                         const int* __restrict__ s2, const int* __restrict__ d2) {
    int i = blockIdx.x * blockDim.x + threadIdx.x;
    if (i < NE1) {
        int d = d1[i];
        int p = atomicAdd(&g_deg1[d], 1);
        if (p < CAP1) g_slot1[(size_t)d * CAP1 + p] = s1[i];
    } else {
        int e = i - NE1;
        int d = d2[e];
        int p = atomicAdd(&g_deg2[d], 1);
        if (p < CAP2) g_slot2[(size_t)d * CAP2 + p] = s2[e];
    }
}

// ================= gather: out[d] = base[d] + sum_i table[slot[d][i]] =================
// Half-warp per destination; 4-way ILP on the L2-latency chain, int4 slot loads.
template <int CAP>
__global__ void __launch_bounds__(256) gather(const int* __restrict__ deg,
                                              const int* __restrict__ slot,
                                              const float4* __restrict__ table,
                                              const float4* __restrict__ base,
                                              float4* __restrict__ out) {
    const int hw = (blockIdx.x * blockDim.x + threadIdx.x) >> 4;
    const int q = threadIdx.x & 15;
    int dg = deg[hw];
    if (dg > CAP) dg = CAP;
    const int* sl = slot + (size_t)hw * CAP;
    float4 v = base[hw * 16 + q];
    float4 u1 = make_float4(0.f, 0.f, 0.f, 0.f);
    float4 u2 = make_float4(0.f, 0.f, 0.f, 0.f);
    float4 u3 = make_float4(0.f, 0.f, 0.f, 0.f);
    int i = 0;
    for (; i + 4 <= dg; i += 4) {
        int4 s = *(const int4*)(sl + i);
        float4 t0 = table[(size_t)s.x * 16 + q];
        float4 t1 = table[(size_t)s.y * 16 + q];
        float4 t2 = table[(size_t)s.z * 16 + q];
        float4 t3 = table[(size_t)s.w * 16 + q];
        v.x += t0.x;  v.y += t0.y;  v.z += t0.z;  v.w += t0.w;
        u1.x += t1.x; u1.y += t1.y; u1.z += t1.z; u1.w += t1.w;
        u2.x += t2.x; u2.y += t2.y; u2.z += t2.z; u2.w += t2.w;
        u3.x += t3.x; u3.y += t3.y; u3.z += t3.z; u3.w += t3.w;
    }
    for (; i < dg; i++) {
        float4 t = table[(size_t)__ldg(sl + i) * 16 + q];
        v.x += t.x; v.y += t.y; v.z += t.z; v.w += t.w;
    }
    v.x += u1.x + u2.x + u3.x;
    v.y += u1.y + u2.y + u3.y;
    v.z += u1.z + u2.z + u3.z;
    v.w += u1.w + u2.w + u3.w;
    out[hw * 16 + q] = v;
}

// ================= task head: x2[t] = relu(acc2[t]@W3+b3) @ W4 + b4 =================
__global__ void __launch_bounds__(256) task_head(const float* __restrict__ acc2,
                                                 const float* __restrict__ W3,
                                                 const float* __restrict__ b3,
                                                 const float* __restrict__ W4,
                                                 const float* __restrict__ b4,
                                                 float* __restrict__ x2) {
    __shared__ float W3sh[SDIM * SDIM];
    __shared__ float b3sh[SDIM];
    __shared__ float W4sh[SDIM];
    for (int i = threadIdx.x; i < SDIM * SDIM; i += blockDim.x) W3sh[i] = W3[i];
    if (threadIdx.x < SDIM) { b3sh[threadIdx.x] = b3[threadIdx.x]; W4sh[threadIdx.x] = W4[threadIdx.x]; }
    __syncthreads();

    const int warp = threadIdx.x >> 5;
    const int lane = threadIdx.x & 31;
    const int t = blockIdx.x * (blockDim.x >> 5) + warp;

    const float* row = acc2 + (size_t)t * SDIM;
    float s0 = b3sh[lane];
    float s1 = b3sh[lane + 32];
#pragma unroll 4
    for (int k = 0; k < SDIM; k++) {
        float a = __ldg(row + k);
        s0 = fmaf(a, W3sh[k * SDIM + lane], s0);
        s1 = fmaf(a, W3sh[k * SDIM + lane + 32], s1);
    }
    float p = fmaxf(s0, 0.0f) * W4sh[lane] + fmaxf(s1, 0.0f) * W4sh[lane + 32];
#pragma unroll
    for (int o = 16; o; o >>= 1) p += __shfl_xor_sync(0xffffffffu, p, o);
    if (lane == 0) x2[t] = p + b4[0];
}

// ================= pooling + critic: one warp per graph =================
__global__ void __launch_bounds__(256) pool_critic(const float* __restrict__ x2,
                                                   const float* __restrict__ Wc1,
                                                   const float* __restrict__ bc1,
                                                   const float* __restrict__ Wc2,
                                                   const float* __restrict__ bc2,
                                                   float* __restrict__ out) {
    const int warp = (blockIdx.x * blockDim.x + threadIdx.x) >> 5;
    const int lane = threadIdx.x & 31;
    if (warp >= NB) return;
    float v = x2[warp * 32 + lane];
    float mx = v, sm = v;
#pragma unroll
    for (int o = 16; o; o >>= 1) {
        mx = fmaxf(mx, __shfl_xor_sync(0xffffffffu, mx, o));
        sm += __shfl_xor_sync(0xffffffffu, sm, o);
    }
    if (lane == 0) {
        float mean = sm * (1.0f / 32.0f);
        float r = bc2[0];
#pragma unroll
        for (int i = 0; i < 8; i++) {
            float h = fmaxf(fmaf(mx, Wc1[i], fmaf(mean, Wc1[8 + i], bc1[i])), 0.0f);
            r = fmaf(h, Wc2[i], r);
        }
        out[warp] = r;
    }
}

extern "C" void kernel_launch(void* const* d_in, const int* in_sizes, int n_in,
                              void* d_out, int out_size) {
    const float* x_goal = (const float*)d_in[0];
    const float* x_obs  = (const float*)d_in[1];
    const float* x_task = (const float*)d_in[2];
    const int* ei_go_src = (const int*)d_in[3];
    const int* ei_go_dst = (const int*)d_in[4];
    const int* ei_ot_src = (const int*)d_in[5];
    const int* ei_ot_dst = (const int*)d_in[6];
    // d_in[7] = task_batch (contiguous 32/graph; unused)
    const float* W1  = (const float*)d_in[8];
    const float* b1  = (const float*)d_in[9];
    const float* W2  = (const float*)d_in[10];
    const float* b2  = (const float*)d_in[11];
    const float* W3  = (const float*)d_in[12];
    const float* b3  = (const float*)d_in[13];
    const float* W4  = (const float*)d_in[14];
    const float* b4  = (const float*)d_in[15];
    const float* Wc1 = (const float*)d_in[16];
    const float* bc1 = (const float*)d_in[17];
    const float* Wc2 = (const float*)d_in[18];
    const float* bc2 = (const float*)d_in[19];
    float* out = (float*)d_out;

    float *goalT, *acc1, *x1, *acc2, *x2;
    int *deg1, *deg2, *slot1, *slot2;
    cudaGetSymbolAddress((void**)&goalT, g_goalT);
    cudaGetSymbolAddress((void**)&acc1, g_acc1);
    cudaGetSymbolAddress((void**)&x1, g_x1);
    cudaGetSymbolAddress((void**)&acc2, g_acc2);
    cudaGetSymbolAddress((void**)&x2, g_x2);
    cudaGetSymbolAddress((void**)&deg1, g_deg1);
    cudaGetSymbolAddress((void**)&deg2, g_deg2);
    cudaGetSymbolAddress((void**)&slot1, g_slot1);
    cudaGetSymbolAddress((void**)&slot2, g_slot2);

    // --- CSR buckets ---
    zero_deg<<<(NOBS + NTASK) / 256, 256>>>();
    fill_csr<<<(NE1 + NE2) / 256, 256>>>(ei_go_src, ei_go_dst, ei_ot_src, ei_ot_dst);

    // --- goalT = x_goal @ W1 (W1 pushed through aggregation) ---
    gemm_v5<FDIM, false, false, false><<<NGOAL / 128, 256>>>(x_goal, W1, b1, goalT);
    // --- acc1 = x_obs @ W1 + b1 ---
    gemm_v5<FDIM, false, false, true><<<NOBS / 128, 256>>>(x_obs, W1, b1, acc1);
    // --- acc1[d] += sum goalT[src in bucket(d)] ---
    gather<CAP1><<<NOBS * 16 / 256, 256>>>(deg1, slot1, (const float4*)goalT,
                                           (const float4*)acc1, (float4*)acc1);
    // --- x1 = relu(relu(acc1) @ W2 + b2) ---
    gemm_v5<SDIM, true, true, true><<<NOBS / 128, 256>>>(acc1, W2, b2, x1);
    // --- acc2[d] = x_task[d] + sum x1[src in bucket(d)] ---
    gather<CAP2><<<NTASK * 16 / 256, 256>>>(deg2, slot2, (const float4*)x1,
                                            (const float4*)x_task, (float4*)acc2);
    // --- x2[t] = relu(acc2[t]@W3+b3) @ W4 + b4 ---
    task_head<<<NTASK / 8, 256>>>(acc2, W3, b3, W4, b4, x2);
    // --- per-graph max/mean pool + critic ---
    pool_critic<<<(NB * 32 + 255) / 256, 256>>>(x2, Wc1, bc1, Wc2, bc2, out);
}